// round 5
// baseline (speedup 1.0000x reference)
#include <cuda_runtime.h>
#include <cstdint>

#define N_NODES 50000
#define N_EDGES 800000

// ---------------- device scratch (allocation-free rule: __device__ globals) ----
__device__ __align__(16) float g_dinv[N_NODES];
__device__ __align__(16) float g_h  [N_NODES * 64];   // GEMM output of current layer
__device__ __align__(16) float g_x1 [N_NODES * 64];   // layer-1 activation
__device__ __align__(16) float g_x2 [N_NODES * 64];   // layer-2 activation
__device__ int   g_deg [N_NODES];
__device__ int   g_ptr [N_NODES + 1];
__device__ int   g_fill[N_NODES];
__device__ int   g_csr_src[N_EDGES];
__device__ float g_csr_w  [N_EDGES];

// ---------------- degree -------------------------------------------------------
__global__ void k_init_deg(int* deg) {
    int i = blockIdx.x * blockDim.x + threadIdx.x;
    if (i < N_NODES) deg[i] = 0;
}

__global__ void k_count_deg(const int* __restrict__ ei, int* deg) {
    int e = blockIdx.x * blockDim.x + threadIdx.x;
    if (e < N_EDGES) atomicAdd(&deg[ei[N_EDGES + e]], 1);
}

// ---- fused single-block scan: deg -> ptr/fill (exclusive) + dinv ---------------
// 1024 threads, each owns a contiguous chunk of ceil(N/1024)=49 nodes.
__global__ void k_scan_fused(const int* __restrict__ deg, int* __restrict__ ptr,
                             int* __restrict__ fill, float* __restrict__ dinv) {
    constexpr int T = 1024;
    constexpr int CHUNK = (N_NODES + T - 1) / T;  // 49
    __shared__ int s[T];
    int t = threadIdx.x;
    int lo = t * CHUNK;
    int hi = min(lo + CHUNK, N_NODES);

    // local chunk sum
    int sum = 0;
    for (int i = lo; i < hi; i++) sum += deg[i];
    s[t] = sum;
    __syncthreads();

    // inclusive scan of 1024 chunk sums
    for (int o = 1; o < T; o <<= 1) {
        int u = (t >= o) ? s[t - o] : 0;
        __syncthreads();
        s[t] += u;
        __syncthreads();
    }
    int run = s[t] - sum;  // exclusive prefix for this chunk

    // write per-node exclusive prefix + dinv
    for (int i = lo; i < hi; i++) {
        int d = deg[i];
        ptr[i]  = run;
        fill[i] = run;
        dinv[i] = rsqrtf((float)d + 1.0f);  // +1 self-loop
        run += d;
    }
    if (t == T - 1) ptr[N_NODES] = N_EDGES;
}

// ---------------- counting-sort fill: CSR by dst --------------------------------
__global__ void k_fill(const int* __restrict__ ei, const float* __restrict__ dinv,
                       int* fill, int* __restrict__ csr_src, float* __restrict__ csr_w) {
    int e = blockIdx.x * blockDim.x + threadIdx.x;
    if (e >= N_EDGES) return;
    int s = ei[e];
    int d = ei[N_EDGES + e];
    int pos = atomicAdd(&fill[d], 1);
    csr_src[pos] = s;
    csr_w[pos]   = dinv[s] * dinv[d];
}

// ---------------- small GEMM: H[N, DOUT] = X[N, 64] @ W[64, DOUT] ---------------
// Each thread computes one float4 of output: 1 broadcast LDS + 1 LDS.128 per 4 FMA.
template <int DOUT>
__global__ void k_gemm(const float* __restrict__ X, const float* __restrict__ W,
                       float* __restrict__ H) {
    constexpr int DIN  = 64;
    constexpr int C4   = DOUT / 4;         // float4 cols per row: 16 or 8
    constexpr int ROWS = 256 / C4;         // rows per block: 16 or 32
    constexpr int XS   = 17;               // padded row stride in float4 (68 floats)
    __shared__ float4 sW[DIN * C4];        // W as [k][c4]
    __shared__ float4 sX4[ROWS * XS];

    int tid = threadIdx.x;
    // load W (row-major [64][DOUT]) as float4
    for (int i = tid; i < DIN * C4; i += 256)
        sW[i] = ((const float4*)W)[i];

    int rowbase = blockIdx.x * ROWS;
    // load X tile, padded stride to avoid bank conflicts between rows
    for (int i = tid; i < ROWS * (DIN / 4); i += 256) {
        int r = i / (DIN / 4);
        int q = i % (DIN / 4);
        int row = rowbase + r;
        sX4[r * XS + q] = (row < N_NODES)
            ? ((const float4*)X)[(size_t)row * (DIN / 4) + q]
            : make_float4(0.f, 0.f, 0.f, 0.f);
    }
    __syncthreads();

    int c4  = tid % C4;
    int r   = tid / C4;
    int row = rowbase + r;
    if (row >= N_NODES) return;

    const float* sx = (const float*)&sX4[r * XS];
    float4 acc = make_float4(0.f, 0.f, 0.f, 0.f);
#pragma unroll
    for (int k = 0; k < DIN; k++) {
        float  xv = sx[k];
        float4 wv = sW[k * C4 + c4];
        acc.x = fmaf(xv, wv.x, acc.x);
        acc.y = fmaf(xv, wv.y, acc.y);
        acc.z = fmaf(xv, wv.z, acc.z);
        acc.w = fmaf(xv, wv.w, acc.w);
    }
    ((float4*)H)[(size_t)row * C4 + c4] = acc;
}

// ---- fused pull aggregation + self-loop + bias + activation --------------------
// C = DOUT/4 threads per node, each owning one float4 lane.
template <int DOUT, bool TANH>
__global__ void k_agg(const int* __restrict__ ptr, const int* __restrict__ csr_src,
                      const float* __restrict__ csr_w,
                      const float* __restrict__ H, const float* __restrict__ dinv,
                      const float* __restrict__ b, float* __restrict__ OUT) {
    constexpr int C   = DOUT / 4;     // 16 (d=64) or 8 (d=32)
    constexpr int NPB = 256 / C;      // nodes per block
    int lane = threadIdx.x % C;
    int node = blockIdx.x * NPB + threadIdx.x / C;
    if (node >= N_NODES) return;

    int beg = ptr[node];
    int end = ptr[node + 1];
    const float4* H4 = (const float4*)H;

    float4 acc = make_float4(0.f, 0.f, 0.f, 0.f);
    int e = beg;
    // 4-deep software pipeline for memory-level parallelism
    for (; e + 3 < end; e += 4) {
        int    s0 = csr_src[e],     s1 = csr_src[e + 1];
        int    s2 = csr_src[e + 2], s3 = csr_src[e + 3];
        float  w0 = csr_w[e],       w1 = csr_w[e + 1];
        float  w2 = csr_w[e + 2],   w3 = csr_w[e + 3];
        float4 v0 = H4[(size_t)s0 * C + lane];
        float4 v1 = H4[(size_t)s1 * C + lane];
        float4 v2 = H4[(size_t)s2 * C + lane];
        float4 v3 = H4[(size_t)s3 * C + lane];
        acc.x += v0.x * w0 + v1.x * w1 + v2.x * w2 + v3.x * w3;
        acc.y += v0.y * w0 + v1.y * w1 + v2.y * w2 + v3.y * w3;
        acc.z += v0.z * w0 + v1.z * w1 + v2.z * w2 + v3.z * w3;
        acc.w += v0.w * w0 + v1.w * w1 + v2.w * w2 + v3.w * w3;
    }
    for (; e < end; e++) {
        int    s0 = csr_src[e];
        float  w0 = csr_w[e];
        float4 v0 = H4[(size_t)s0 * C + lane];
        acc.x += v0.x * w0;
        acc.y += v0.y * w0;
        acc.z += v0.z * w0;
        acc.w += v0.w * w0;
    }

    float di = dinv[node];
    float sl = di * di;                       // self-loop weight
    float4 hh = H4[(size_t)node * C + lane];
    float4 bb = ((const float4*)b)[lane];
    float4 v;
    v.x = acc.x + hh.x * sl + bb.x;
    v.y = acc.y + hh.y * sl + bb.y;
    v.z = acc.z + hh.z * sl + bb.z;
    v.w = acc.w + hh.w * sl + bb.w;
    if (TANH) {
        v.x = tanhf(v.x); v.y = tanhf(v.y); v.z = tanhf(v.z); v.w = tanhf(v.w);
    }
    ((float4*)OUT)[(size_t)node * C + lane] = v;
}

// ---------------- launch --------------------------------------------------------
static inline int cdiv(long long a, int b) { return (int)((a + b - 1) / b); }

extern "C" void kernel_launch(void* const* d_in, const int* in_sizes, int n_in,
                              void* d_out, int out_size) {
    const float* x  = (const float*)d_in[0];
    const int*   ei = (const int*)d_in[1];      // JAX x64 disabled: int64 -> int32
    const float* W1 = (const float*)d_in[2];
    const float* b1 = (const float*)d_in[3];
    const float* W2 = (const float*)d_in[4];
    const float* b2 = (const float*)d_in[5];
    const float* W3 = (const float*)d_in[6];
    const float* b3 = (const float*)d_in[7];
    float*       out = (float*)d_out;

    float *dinv, *h, *x1, *x2, *csr_w;
    int   *deg, *ptr, *fill, *csr_src;
    cudaGetSymbolAddress((void**)&dinv,    g_dinv);
    cudaGetSymbolAddress((void**)&h,       g_h);
    cudaGetSymbolAddress((void**)&x1,      g_x1);
    cudaGetSymbolAddress((void**)&x2,      g_x2);
    cudaGetSymbolAddress((void**)&deg,     g_deg);
    cudaGetSymbolAddress((void**)&ptr,     g_ptr);
    cudaGetSymbolAddress((void**)&fill,    g_fill);
    cudaGetSymbolAddress((void**)&csr_src, g_csr_src);
    cudaGetSymbolAddress((void**)&csr_w,   g_csr_w);

    const int T = 256;

    // ---- CSR build + norm ----
    k_init_deg  <<<cdiv(N_NODES, T), T>>>(deg);
    k_count_deg <<<cdiv(N_EDGES, T), T>>>(ei, deg);
    k_scan_fused<<<1, 1024>>>(deg, ptr, fill, dinv);
    k_fill      <<<cdiv(N_EDGES, T), T>>>(ei, dinv, fill, csr_src, csr_w);

    // ---- layer 1: x -> x1 (tanh) ----
    k_gemm<64><<<cdiv(N_NODES, 16), T>>>(x, W1, h);
    k_agg<64, true><<<cdiv(N_NODES * 16, T), T>>>(ptr, csr_src, csr_w, h, dinv, b1, x1);

    // ---- layer 2: x1 -> x2 (tanh) ----
    k_gemm<64><<<cdiv(N_NODES, 16), T>>>(x1, W2, h);
    k_agg<64, true><<<cdiv(N_NODES * 16, T), T>>>(ptr, csr_src, csr_w, h, dinv, b2, x2);

    // ---- layer 3: x2 -> out (linear) ----
    k_gemm<32><<<cdiv(N_NODES, 32), T>>>(x2, W3, h);
    k_agg<32, false><<<cdiv(N_NODES * 8, T), T>>>(ptr, csr_src, csr_w, h, dinv, b3, out);
}

// round 6
// speedup vs baseline: 1.5460x; 1.5460x over previous
#include <cuda_runtime.h>
#include <cstdint>

#define N_NODES 50000
#define N_EDGES 800000
#define NB_SCAN 196          // ceil(50000/256)

// ---------------- device scratch (allocation-free rule: __device__ globals) ----
__device__ __align__(16) float g_dinv[N_NODES];
__device__ __align__(16) float g_h  [N_NODES * 64];   // GEMM output of current layer
__device__ __align__(16) float g_x1 [N_NODES * 64];   // layer-1 activation
__device__ __align__(16) float g_x2 [N_NODES * 64];   // layer-2 activation
__device__ int   g_deg [N_NODES];
__device__ int   g_ptr [N_NODES + 1];
__device__ int   g_fill[N_NODES];
__device__ int   g_bsum[NB_SCAN];
__device__ int   g_csr_src[N_EDGES];
__device__ float g_csr_w  [N_EDGES];

// ---------------- degree -------------------------------------------------------
__global__ void k_init_deg(int* deg) {
    int i = blockIdx.x * blockDim.x + threadIdx.x;
    if (i < N_NODES) deg[i] = 0;
}

__global__ void k_count_deg(const int* __restrict__ ei, int* deg) {
    int e = blockIdx.x * blockDim.x + threadIdx.x;
    if (e < N_EDGES) atomicAdd(&deg[ei[N_EDGES + e]], 1);
}

// ---------------- 3-kernel exclusive scan of deg -> ptr (multi-block, coalesced)
__global__ void k_scanA(const int* __restrict__ deg, int* __restrict__ bsum) {
    __shared__ int s[256];
    int t = threadIdx.x;
    int i = blockIdx.x * 256 + t;
    s[t] = (i < N_NODES) ? deg[i] : 0;
    __syncthreads();
    for (int o = 128; o > 0; o >>= 1) {
        if (t < o) s[t] += s[t + o];
        __syncthreads();
    }
    if (t == 0) bsum[blockIdx.x] = s[0];
}

__global__ void k_scanB(int* bsum) {
    __shared__ int s[256];
    int t = threadIdx.x;
    int v = (t < NB_SCAN) ? bsum[t] : 0;
    s[t] = v;
    __syncthreads();
    for (int o = 1; o < 256; o <<= 1) {
        int u = (t >= o) ? s[t - o] : 0;
        __syncthreads();
        s[t] += u;
        __syncthreads();
    }
    if (t < NB_SCAN) bsum[t] = s[t] - v;  // exclusive
}

__global__ void k_scanC(const int* __restrict__ deg, const int* __restrict__ bsum,
                        int* __restrict__ ptr, int* __restrict__ fill,
                        float* __restrict__ dinv) {
    __shared__ int s[256];
    int t = threadIdx.x;
    int i = blockIdx.x * 256 + t;
    int v = (i < N_NODES) ? deg[i] : 0;
    s[t] = v;
    __syncthreads();
    for (int o = 1; o < 256; o <<= 1) {
        int u = (t >= o) ? s[t - o] : 0;
        __syncthreads();
        s[t] += u;
        __syncthreads();
    }
    int excl = s[t] - v + bsum[blockIdx.x];
    if (i < N_NODES) {
        ptr[i]  = excl;
        fill[i] = excl;
        dinv[i] = rsqrtf((float)v + 1.0f);  // +1 self-loop
    }
    if (i == N_NODES) ptr[N_NODES] = N_EDGES;
}

// ---------------- counting-sort fill: CSR by dst --------------------------------
__global__ void k_fill(const int* __restrict__ ei, const float* __restrict__ dinv,
                       int* fill, int* __restrict__ csr_src, float* __restrict__ csr_w) {
    int e = blockIdx.x * blockDim.x + threadIdx.x;
    if (e >= N_EDGES) return;
    int s = ei[e];
    int d = ei[N_EDGES + e];
    int pos = atomicAdd(&fill[d], 1);
    csr_src[pos] = s;
    csr_w[pos]   = dinv[s] * dinv[d];
}

// ---------------- small GEMM: H[N, DOUT] = X[N, 64] @ W[64, DOUT] ---------------
// Each thread computes one float4 of output: 1 broadcast LDS + 1 LDS.128 per 4 FMA.
template <int DOUT>
__global__ void k_gemm(const float* __restrict__ X, const float* __restrict__ W,
                       float* __restrict__ H) {
    constexpr int DIN  = 64;
    constexpr int C4   = DOUT / 4;         // float4 cols per row: 16 or 8
    constexpr int ROWS = 256 / C4;         // rows per block: 16 or 32
    constexpr int XS   = 17;               // padded row stride in float4 (68 floats)
    __shared__ float4 sW[DIN * C4];        // W as [k][c4]
    __shared__ float4 sX4[ROWS * XS];

    int tid = threadIdx.x;
    // load W (row-major [64][DOUT]) as float4
    for (int i = tid; i < DIN * C4; i += 256)
        sW[i] = ((const float4*)W)[i];

    int rowbase = blockIdx.x * ROWS;
    // load X tile, padded stride to avoid bank conflicts between rows
    for (int i = tid; i < ROWS * (DIN / 4); i += 256) {
        int r = i / (DIN / 4);
        int q = i % (DIN / 4);
        int row = rowbase + r;
        sX4[r * XS + q] = (row < N_NODES)
            ? ((const float4*)X)[(size_t)row * (DIN / 4) + q]
            : make_float4(0.f, 0.f, 0.f, 0.f);
    }
    __syncthreads();

    int c4  = tid % C4;
    int r   = tid / C4;
    int row = rowbase + r;
    if (row >= N_NODES) return;

    const float* sx = (const float*)&sX4[r * XS];
    float4 acc = make_float4(0.f, 0.f, 0.f, 0.f);
#pragma unroll
    for (int k = 0; k < DIN; k++) {
        float  xv = sx[k];
        float4 wv = sW[k * C4 + c4];
        acc.x = fmaf(xv, wv.x, acc.x);
        acc.y = fmaf(xv, wv.y, acc.y);
        acc.z = fmaf(xv, wv.z, acc.z);
        acc.w = fmaf(xv, wv.w, acc.w);
    }
    ((float4*)H)[(size_t)row * C4 + c4] = acc;
}

// ---- fused pull aggregation + self-loop + bias + activation --------------------
// C = DOUT/4 threads per node, each owning one float4 lane.
template <int DOUT, bool TANH>
__global__ void k_agg(const int* __restrict__ ptr, const int* __restrict__ csr_src,
                      const float* __restrict__ csr_w,
                      const float* __restrict__ H, const float* __restrict__ dinv,
                      const float* __restrict__ b, float* __restrict__ OUT) {
    constexpr int C   = DOUT / 4;     // 16 (d=64) or 8 (d=32)
    constexpr int NPB = 256 / C;      // nodes per block
    int lane = threadIdx.x % C;
    int node = blockIdx.x * NPB + threadIdx.x / C;
    if (node >= N_NODES) return;

    int beg = ptr[node];
    int end = ptr[node + 1];
    const float4* H4 = (const float4*)H;

    float4 acc = make_float4(0.f, 0.f, 0.f, 0.f);
    int e = beg;
    // 4-deep software pipeline for memory-level parallelism
    for (; e + 3 < end; e += 4) {
        int    s0 = csr_src[e],     s1 = csr_src[e + 1];
        int    s2 = csr_src[e + 2], s3 = csr_src[e + 3];
        float  w0 = csr_w[e],       w1 = csr_w[e + 1];
        float  w2 = csr_w[e + 2],   w3 = csr_w[e + 3];
        float4 v0 = H4[(size_t)s0 * C + lane];
        float4 v1 = H4[(size_t)s1 * C + lane];
        float4 v2 = H4[(size_t)s2 * C + lane];
        float4 v3 = H4[(size_t)s3 * C + lane];
        acc.x += v0.x * w0 + v1.x * w1 + v2.x * w2 + v3.x * w3;
        acc.y += v0.y * w0 + v1.y * w1 + v2.y * w2 + v3.y * w3;
        acc.z += v0.z * w0 + v1.z * w1 + v2.z * w2 + v3.z * w3;
        acc.w += v0.w * w0 + v1.w * w1 + v2.w * w2 + v3.w * w3;
    }
    for (; e < end; e++) {
        int    s0 = csr_src[e];
        float  w0 = csr_w[e];
        float4 v0 = H4[(size_t)s0 * C + lane];
        acc.x += v0.x * w0;
        acc.y += v0.y * w0;
        acc.z += v0.z * w0;
        acc.w += v0.w * w0;
    }

    float di = dinv[node];
    float sl = di * di;                       // self-loop weight
    float4 hh = H4[(size_t)node * C + lane];
    float4 bb = ((const float4*)b)[lane];
    float4 v;
    v.x = acc.x + hh.x * sl + bb.x;
    v.y = acc.y + hh.y * sl + bb.y;
    v.z = acc.z + hh.z * sl + bb.z;
    v.w = acc.w + hh.w * sl + bb.w;
    if (TANH) {
        v.x = tanhf(v.x); v.y = tanhf(v.y); v.z = tanhf(v.z); v.w = tanhf(v.w);
    }
    ((float4*)OUT)[(size_t)node * C + lane] = v;
}

// ---------------- launch --------------------------------------------------------
static inline int cdiv(long long a, int b) { return (int)((a + b - 1) / b); }

extern "C" void kernel_launch(void* const* d_in, const int* in_sizes, int n_in,
                              void* d_out, int out_size) {
    const float* x  = (const float*)d_in[0];
    const int*   ei = (const int*)d_in[1];      // JAX x64 disabled: int64 -> int32
    const float* W1 = (const float*)d_in[2];
    const float* b1 = (const float*)d_in[3];
    const float* W2 = (const float*)d_in[4];
    const float* b2 = (const float*)d_in[5];
    const float* W3 = (const float*)d_in[6];
    const float* b3 = (const float*)d_in[7];
    float*       out = (float*)d_out;

    float *dinv, *h, *x1, *x2, *csr_w;
    int   *deg, *ptr, *fill, *bsum, *csr_src;
    cudaGetSymbolAddress((void**)&dinv,    g_dinv);
    cudaGetSymbolAddress((void**)&h,       g_h);
    cudaGetSymbolAddress((void**)&x1,      g_x1);
    cudaGetSymbolAddress((void**)&x2,      g_x2);
    cudaGetSymbolAddress((void**)&deg,     g_deg);
    cudaGetSymbolAddress((void**)&ptr,     g_ptr);
    cudaGetSymbolAddress((void**)&fill,    g_fill);
    cudaGetSymbolAddress((void**)&bsum,    g_bsum);
    cudaGetSymbolAddress((void**)&csr_src, g_csr_src);
    cudaGetSymbolAddress((void**)&csr_w,   g_csr_w);

    const int T = 256;

    // ---- CSR build + norm ----
    k_init_deg <<<cdiv(N_NODES, T), T>>>(deg);
    k_count_deg<<<cdiv(N_EDGES, T), T>>>(ei, deg);
    k_scanA    <<<NB_SCAN, T>>>(deg, bsum);
    k_scanB    <<<1, T>>>(bsum);
    k_scanC    <<<NB_SCAN, T>>>(deg, bsum, ptr, fill, dinv);
    k_fill     <<<cdiv(N_EDGES, T), T>>>(ei, dinv, fill, csr_src, csr_w);

    // ---- layer 1: x -> x1 (tanh) ----
    k_gemm<64><<<cdiv(N_NODES, 16), T>>>(x, W1, h);
    k_agg<64, true><<<cdiv(N_NODES * 16, T), T>>>(ptr, csr_src, csr_w, h, dinv, b1, x1);

    // ---- layer 2: x1 -> x2 (tanh) ----
    k_gemm<64><<<cdiv(N_NODES, 16), T>>>(x1, W2, h);
    k_agg<64, true><<<cdiv(N_NODES * 16, T), T>>>(ptr, csr_src, csr_w, h, dinv, b2, x2);

    // ---- layer 3: x2 -> out (linear) ----
    k_gemm<32><<<cdiv(N_NODES, 32), T>>>(x2, W3, h);
    k_agg<32, false><<<cdiv(N_NODES * 8, T), T>>>(ptr, csr_src, csr_w, h, dinv, b3, out);
}